// round 15
// baseline (speedup 1.0000x reference)
#include <cuda_runtime.h>
#include <cuda_bf16.h>
#include <math_constants.h>
#include <cstdint>

// ---------------------------------------------------------------------------
// Problem constants
// ---------------------------------------------------------------------------
#define N_ROWS 4096
#define V_SIZE 50000
#define D_DIM  300
#define KP     320      // padded depth (multiple of 32)
#define VP     50048    // padded vocab count = 391*128
#define DOUT   384      // padded output width = 3*128
#define NSPLIT 6        // gemm2 K-splits
#define NVT    (VP / 128)   // 391 vocab tiles (gemm1 grid.x)
#define NLT    49           // expsplit col-blocks per row

#define BM_T   256      // CTA tile rows   (A)
#define BN_T   128      // CTA tile cols   (B)
#define NTH    512      // threads per CTA (16 warps)

#define KC     32       // K-chunk
#define NSTG   3        // pipeline stages

// ---------------------------------------------------------------------------
// Scratch (__device__ globals)
// ---------------------------------------------------------------------------
__device__ float         g_Y    [N_ROWS * KP];
__device__ __nv_bfloat16 g_Yhi  [N_ROWS * KP];
__device__ __nv_bfloat16 g_Ylo  [N_ROWS * KP];
__device__ __nv_bfloat16 g_Vhi  [(size_t)VP * KP];
__device__ __nv_bfloat16 g_Vlo  [(size_t)VP * KP];
__device__ __nv_bfloat16 g_VThi [(size_t)DOUT * VP];
__device__ __nv_bfloat16 g_VTlo [(size_t)DOUT * VP];
__device__ float         g_S    [(size_t)N_ROWS * VP];
__device__ __nv_bfloat16 g_Phi  [(size_t)N_ROWS * VP];
__device__ __nv_bfloat16 g_Plo  [(size_t)N_ROWS * VP];
__device__ float         g_mpart[(size_t)N_ROWS * NVT];
__device__ float         g_lpart[(size_t)N_ROWS * NLT];
__device__ float         g_m    [N_ROWS];
__device__ float         g_sdef [N_ROWS];
__device__ float         g_U    [NSPLIT][N_ROWS * DOUT];

// ---------------------------------------------------------------------------
// HMMA + ldmatrix wrappers
// ---------------------------------------------------------------------------
__device__ __forceinline__ void mma16816(float* c, const uint32_t* a, const uint32_t* b) {
    asm volatile(
        "mma.sync.aligned.m16n8k16.row.col.f32.bf16.bf16.f32 "
        "{%0,%1,%2,%3}, {%4,%5,%6,%7}, {%8,%9}, {%0,%1,%2,%3};"
        : "+f"(c[0]), "+f"(c[1]), "+f"(c[2]), "+f"(c[3])
        : "r"(a[0]), "r"(a[1]), "r"(a[2]), "r"(a[3]), "r"(b[0]), "r"(b[1]));
}

__device__ __forceinline__ void ldm_x4(uint32_t* r, uint32_t saddr) {
    asm volatile("ldmatrix.sync.aligned.m8n8.x4.shared.b16 {%0,%1,%2,%3}, [%4];"
                 : "=r"(r[0]), "=r"(r[1]), "=r"(r[2]), "=r"(r[3]) : "r"(saddr));
}

// ---------------------------------------------------------------------------
// smem tile geometry: rows x [32 bf16] with stride 80 B (=20 words)
// (80B stride: ldmatrix 16B phases hit 8 distinct bank-quads, incl. +16B k8)
// stage = Ahi[256r] Alo[256r] Bhi[128r] Blo[128r]; NSTG-stage ring
// ---------------------------------------------------------------------------
#define TS_W      20                         // words per row
#define TS_B      80                         // bytes per row
#define ATILE_W   (BM_T * TS_W)              // 5120 words (20480 B)
#define BTILE_W   (BN_T * TS_W)              // 2560 words (10240 B)
#define STAGE_W   (2 * ATILE_W + 2 * BTILE_W)    // 15360 words (61440 B)
#define STAGE_B   (STAGE_W * 4)
#define GEMM_SMEM (NSTG * STAGE_B)           // 184320 bytes

__device__ __forceinline__ uint32_t smem_u32(const void* p) {
    return (uint32_t)__cvta_generic_to_shared(p);
}

// async copy one [ROWS x 32 bf16] tile; 4 x 16B pieces per row
template <int ROWS>
__device__ __forceinline__ void copy_tile_async(uint32_t* dst,
                                                const __nv_bfloat16* __restrict__ src,
                                                size_t srcStride, int tid) {
#pragma unroll
    for (int it = 0; it < (ROWS * 4 + NTH - 1) / NTH; ++it) {
        const int i = tid + it * NTH;
        if ((ROWS * 4) % NTH != 0 && i >= ROWS * 4) break;
        const int row = i >> 2, q = i & 3;
        const uint32_t saddr = smem_u32(dst + row * TS_W + q * 4);
        const void* gaddr = (const void*)(src + (size_t)row * srcStride + q * 8);
        asm volatile("cp.async.cg.shared.global [%0], [%1], 16;"
                     :: "r"(saddr), "l"(gaddr) : "memory");
    }
}

__device__ __forceinline__ void load_stage(uint32_t* st,
        const __nv_bfloat16* Ahi, const __nv_bfloat16* Alo, size_t sA,
        const __nv_bfloat16* Bhi, const __nv_bfloat16* Blo, size_t sB,
        size_t k0, int tid) {
    copy_tile_async<BM_T>(st,                           Ahi + k0, sA, tid);
    copy_tile_async<BM_T>(st + ATILE_W,                 Alo + k0, sA, tid);
    copy_tile_async<BN_T>(st + 2 * ATILE_W,             Bhi + k0, sB, tid);
    copy_tile_async<BN_T>(st + 2 * ATILE_W + BTILE_W,   Blo + k0, sB, tid);
    asm volatile("cp.async.commit_group;" ::: "memory");
}

// ---------------------------------------------------------------------------
// Core CTA-tile GEMM body: 256x128 tile, 16 warps (4m x 4n), warp tile 64x32.
// 3-stage cp.async ring, K-chunk 32, ONE __syncthreads per chunk.
// ---------------------------------------------------------------------------
__device__ __forceinline__ void gemm_body(
        float acc[4][4][4],
        const __nv_bfloat16* Ahi, const __nv_bfloat16* Alo, size_t strideA,
        const __nv_bfloat16* Bhi, const __nv_bfloat16* Blo, size_t strideB,
        int nchunk, uint32_t* smw) {
    const int tid = threadIdx.x;
    const int wid = tid >> 5, lane = tid & 31;
    const int wm0 = (wid >> 2) * 64;         // 4 m-groups
    const int wn0 = (wid & 3) * 32;          // 4 n-groups

    const int aRow = (lane & 7) + ((lane >> 3) & 1) * 8;
    const int aKb  = (lane >> 4) * 16;
    const int bRow = (lane & 7) + (lane >> 4) * 8;
    const int bKb  = ((lane >> 3) & 1) * 16;

    uint32_t aoff[4], boff[2];
#pragma unroll
    for (int i = 0; i < 4; ++i)
        aoff[i] = (uint32_t)((wm0 + 16 * i + aRow) * TS_B + aKb);
#pragma unroll
    for (int p = 0; p < 2; ++p)
        boff[p] = (uint32_t)((wn0 + 16 * p + bRow) * TS_B + bKb);

    const uint32_t sbase = smem_u32(smw);

#pragma unroll
    for (int i = 0; i < 4; ++i)
#pragma unroll
        for (int j = 0; j < 4; ++j)
#pragma unroll
            for (int f = 0; f < 4; ++f) acc[i][j][f] = 0.f;

    // prologue: prefetch stages 0..NSTG-2
    load_stage(smw, Ahi, Alo, strideA, Bhi, Blo, strideB, 0, tid);
    if (nchunk > 1)
        load_stage(smw + STAGE_W, Ahi, Alo, strideA, Bhi, Blo, strideB, KC, tid);

    int stg = 0;
    for (int ch = 0; ch < nchunk; ++ch) {
        if (ch + 2 < nchunk) {
            asm volatile("cp.async.wait_group 1;" ::: "memory");
            __syncthreads();
            // refill the stage consumed at ch-1 (safe: sync above)
            int wstg = stg + 2; if (wstg >= NSTG) wstg -= NSTG;
            load_stage(smw + wstg * STAGE_W,
                       Ahi, Alo, strideA, Bhi, Blo, strideB,
                       (size_t)(ch + 2) * KC, tid);
        } else {
            asm volatile("cp.async.wait_group 0;" ::: "memory");
            __syncthreads();
        }

        const uint32_t st   = sbase + stg * STAGE_B;
        const uint32_t stAh = st;
        const uint32_t stAl = st + ATILE_W * 4;
        const uint32_t stBh = st + 2 * ATILE_W * 4;
        const uint32_t stBl = st + (2 * ATILE_W + BTILE_W) * 4;

#pragma unroll
        for (int ks = 0; ks < 2; ++ks) {     // two k16 steps per 32-chunk
            const uint32_t ko = (uint32_t)(ks * 32);
            uint32_t ah[4][4], al[4][4], bh[2][4], bl[2][4];
#pragma unroll
            for (int p = 0; p < 2; ++p) {
                ldm_x4(bh[p], stBh + boff[p] + ko);
                ldm_x4(bl[p], stBl + boff[p] + ko);
            }
#pragma unroll
            for (int i = 0; i < 4; ++i) {
                ldm_x4(ah[i], stAh + aoff[i] + ko);
                ldm_x4(al[i], stAl + aoff[i] + ko);
            }
#pragma unroll
            for (int i = 0; i < 4; ++i)
#pragma unroll
                for (int j = 0; j < 4; ++j) {
                    const uint32_t* pbh = &bh[j >> 1][(j & 1) * 2];
                    const uint32_t* pbl = &bl[j >> 1][(j & 1) * 2];
                    mma16816(acc[i][j], ah[i], pbh);   // hi*hi
                    mma16816(acc[i][j], ah[i], pbl);   // hi*lo
                    mma16816(acc[i][j], al[i], pbh);   // lo*hi
                }
        }
        if (++stg >= NSTG) stg = 0;
    }
    __syncthreads();   // epilogue may reuse smem
}

// ---------------------------------------------------------------------------
// Kernel 1: Y = words @ W, zero-padded to [4096 x 320], with bf16 hi/lo split
// ---------------------------------------------------------------------------
__global__ void y_prep_kernel(const float* __restrict__ A,
                              const float* __restrict__ B) {
    __shared__ float As[16][16];
    __shared__ float Bs[16][17];
    const int tx = threadIdx.x, ty = threadIdx.y;
    const int row = blockIdx.y * 16 + ty;
    const int col = blockIdx.x * 16 + tx;
    float acc = 0.f;
    for (int k0 = 0; k0 < D_DIM; k0 += 16) {
        As[ty][tx] = (k0 + tx < D_DIM) ? A[row * D_DIM + k0 + tx] : 0.f;
        Bs[ty][tx] = (k0 + ty < D_DIM && col < D_DIM) ? B[(k0 + ty) * D_DIM + col] : 0.f;
        __syncthreads();
#pragma unroll
        for (int kk = 0; kk < 16; ++kk) acc += As[ty][kk] * Bs[kk][tx];
        __syncthreads();
    }
    const int idx = row * KP + col;
    g_Y[idx] = acc;
    __nv_bfloat16 h = __float2bfloat16(acc);
    g_Yhi[idx] = h;
    g_Ylo[idx] = __float2bfloat16(acc - __bfloat162float(h));
}

// ---------------------------------------------------------------------------
// Kernel 2a/2b: vocab splits
// ---------------------------------------------------------------------------
__global__ void v_prep_kernel(const float* __restrict__ vocab) {
    const int idx = blockIdx.x * 256 + threadIdx.x;
    const int v = idx / KP, d = idx - v * KP;
    float val = (v < V_SIZE && d < D_DIM) ? vocab[(size_t)v * D_DIM + d] : 0.f;
    __nv_bfloat16 h = __float2bfloat16(val);
    g_Vhi[idx] = h;
    g_Vlo[idx] = __float2bfloat16(val - __bfloat162float(h));
}

__global__ void vt_prep_kernel(const float* __restrict__ vocab) {
    const int idx = blockIdx.x * 256 + threadIdx.x;
    const int d = idx / VP, v = idx - d * VP;
    float val = (v < V_SIZE && d < D_DIM) ? vocab[(size_t)v * D_DIM + d] : 0.f;
    __nv_bfloat16 h = __float2bfloat16(val);
    g_VThi[idx] = h;
    g_VTlo[idx] = __float2bfloat16(val - __bfloat162float(h));
}

// ---------------------------------------------------------------------------
// Kernel 3: sdef[r] = Y[r] . default_embed
// ---------------------------------------------------------------------------
__global__ void sdef_kernel(const float* __restrict__ de) {
    const int w = (blockIdx.x * blockDim.x + threadIdx.x) >> 5;
    const int lane = threadIdx.x & 31;
    if (w >= N_ROWS) return;
    float s = 0.f;
    for (int d = lane; d < D_DIM; d += 32) s += g_Y[w * KP + d] * de[d];
#pragma unroll
    for (int o = 16; o; o >>= 1) s += __shfl_xor_sync(0xffffffffu, s, o);
    if (lane == 0) g_sdef[w] = s;
}

// ---------------------------------------------------------------------------
// Kernel 4: GEMM-1  S = Y(hi/lo) @ Vocab(hi/lo)^T, fused per-tile row max
// ---------------------------------------------------------------------------
__global__ void __launch_bounds__(NTH, 1) gemm1_kernel() {
    extern __shared__ uint32_t smw[];
    const int v0 = blockIdx.x * BN_T, m0 = blockIdx.y * BM_T;

    float acc[4][4][4];
    gemm_body(acc,
              g_Yhi + (size_t)m0 * KP, g_Ylo + (size_t)m0 * KP, KP,
              g_Vhi + (size_t)v0 * KP, g_Vlo + (size_t)v0 * KP, KP,
              KP / KC, smw);

    const int tid = threadIdx.x, wid = tid >> 5, lane = tid & 31;
    const int g = lane >> 2, t = lane & 3;
    const int wm0 = (wid >> 2) * 64, wn0 = (wid & 3) * 32;

#pragma unroll
    for (int i = 0; i < 4; ++i) {
        const size_t r0 = (size_t)(m0 + wm0 + 16 * i + g);
#pragma unroll
        for (int j = 0; j < 4; ++j) {
            const size_t cc = (size_t)(v0 + wn0 + 8 * j + 2 * t);
            *(float2*)(g_S + r0 * VP + cc)       = make_float2(acc[i][j][0], acc[i][j][1]);
            *(float2*)(g_S + (r0 + 8) * VP + cc) = make_float2(acc[i][j][2], acc[i][j][3]);
        }
    }

    float rm[4][2];
#pragma unroll
    for (int i = 0; i < 4; ++i) { rm[i][0] = -CUDART_INF_F; rm[i][1] = -CUDART_INF_F; }
#pragma unroll
    for (int i = 0; i < 4; ++i)
#pragma unroll
        for (int j = 0; j < 4; ++j) {
            const int c0 = v0 + wn0 + 8 * j + 2 * t;
            const float v00 = (c0     < V_SIZE) ? acc[i][j][0] : -CUDART_INF_F;
            const float v01 = (c0 + 1 < V_SIZE) ? acc[i][j][1] : -CUDART_INF_F;
            const float v10 = (c0     < V_SIZE) ? acc[i][j][2] : -CUDART_INF_F;
            const float v11 = (c0 + 1 < V_SIZE) ? acc[i][j][3] : -CUDART_INF_F;
            rm[i][0] = fmaxf(rm[i][0], fmaxf(v00, v01));
            rm[i][1] = fmaxf(rm[i][1], fmaxf(v10, v11));
        }
#pragma unroll
    for (int i = 0; i < 4; ++i)
#pragma unroll
        for (int h = 0; h < 2; ++h) {
            rm[i][h] = fmaxf(rm[i][h], __shfl_xor_sync(0xffffffffu, rm[i][h], 1));
            rm[i][h] = fmaxf(rm[i][h], __shfl_xor_sync(0xffffffffu, rm[i][h], 2));
        }
    float* red = (float*)smw;                 // [4 n-groups][256 rows]
    if (t == 0) {
#pragma unroll
        for (int i = 0; i < 4; ++i)
#pragma unroll
            for (int h = 0; h < 2; ++h)
                red[(wid & 3) * BM_T + wm0 + 16 * i + g + 8 * h] = rm[i][h];
    }
    __syncthreads();
    if (tid < BM_T) {
        const float mx = fmaxf(fmaxf(red[tid], red[BM_T + tid]),
                               fmaxf(red[2 * BM_T + tid], red[3 * BM_T + tid]));
        g_mpart[(size_t)(m0 + tid) * NVT + blockIdx.x] = mx;
    }
}

// ---------------------------------------------------------------------------
// Kernel 5: g_m[r] = max over tile maxima
// ---------------------------------------------------------------------------
__global__ void reduce_m_kernel() {
    const int w = (blockIdx.x * blockDim.x + threadIdx.x) >> 5;
    const int lane = threadIdx.x & 31;
    if (w >= N_ROWS) return;
    float m = -CUDART_INF_F;
    for (int c = lane; c < NVT; c += 32) m = fmaxf(m, g_mpart[(size_t)w * NVT + c]);
#pragma unroll
    for (int o = 16; o; o >>= 1) m = fmaxf(m, __shfl_xor_sync(0xffffffffu, m, o));
    if (lane == 0) g_m[w] = m;
}

// ---------------------------------------------------------------------------
// Kernel 6: P~ = exp(S - m) -> bf16 hi/lo, fused partial row sums
// ---------------------------------------------------------------------------
__global__ void expsplit_kernel() {
    const int r = blockIdx.y;
    const int tid = threadIdx.x;
    const int c = (blockIdx.x * 256 + tid) * 4;
    const float mrow = g_m[r];
    float lsum = 0.f;
    if (c < VP) {
        const float4 s = *(const float4*)(g_S + (size_t)r * VP + c);
        float p[4];
        p[0] = (c + 0 < V_SIZE) ? __expf(s.x - mrow) : 0.f;
        p[1] = (c + 1 < V_SIZE) ? __expf(s.y - mrow) : 0.f;
        p[2] = (c + 2 < V_SIZE) ? __expf(s.z - mrow) : 0.f;
        p[3] = (c + 3 < V_SIZE) ? __expf(s.w - mrow) : 0.f;
        lsum = (p[0] + p[1]) + (p[2] + p[3]);
        unsigned hi[4], lo[4];
#pragma unroll
        for (int j = 0; j < 4; ++j) {
            const __nv_bfloat16 h = __float2bfloat16(p[j]);
            hi[j] = (unsigned)__bfloat16_as_ushort(h);
            lo[j] = (unsigned)__bfloat16_as_ushort(__float2bfloat16(p[j] - __bfloat162float(h)));
        }
        uint2 hv, lv;
        hv.x = hi[0] | (hi[1] << 16); hv.y = hi[2] | (hi[3] << 16);
        lv.x = lo[0] | (lo[1] << 16); lv.y = lo[2] | (lo[3] << 16);
        *(uint2*)(g_Phi + (size_t)r * VP + c) = hv;
        *(uint2*)(g_Plo + (size_t)r * VP + c) = lv;
    }
#pragma unroll
    for (int o = 16; o; o >>= 1) lsum += __shfl_xor_sync(0xffffffffu, lsum, o);
    __shared__ float sl8[8];
    if ((tid & 31) == 0) sl8[tid >> 5] = lsum;
    __syncthreads();
    if (tid == 0) {
        float L = 0.f;
#pragma unroll
        for (int w = 0; w < 8; ++w) L += sl8[w];
        g_lpart[(size_t)r * NLT + blockIdx.x] = L;
    }
}

// ---------------------------------------------------------------------------
// Kernel 7: GEMM-2  U[split] = P~(hi/lo) @ Vocab(hi/lo); K split over vocab
// ---------------------------------------------------------------------------
__global__ void __launch_bounds__(NTH, 1) gemm2_kernel() {
    extern __shared__ uint32_t smw[];
    const int n0 = blockIdx.x * BN_T, m0 = blockIdx.y * BM_T, sp = blockIdx.z;

    const int tot  = VP / KC;                 // 1564 chunks
    const int base = tot / NSPLIT;
    const int rem  = tot % NSPLIT;
    const int cbeg = sp * base + min(sp, rem);
    const int nch  = base + (sp < rem ? 1 : 0);
    const size_t k0 = (size_t)cbeg * KC;

    float acc[4][4][4];
    gemm_body(acc,
              g_Phi  + (size_t)m0 * VP + k0, g_Plo  + (size_t)m0 * VP + k0, VP,
              g_VThi + (size_t)n0 * VP + k0, g_VTlo + (size_t)n0 * VP + k0, VP,
              nch, smw);

    const int tid = threadIdx.x, wid = tid >> 5, lane = tid & 31;
    const int g = lane >> 2, t = lane & 3;
    const int wm0 = (wid >> 2) * 64, wn0 = (wid & 3) * 32;
    float* U = g_U[sp];
#pragma unroll
    for (int i = 0; i < 4; ++i) {
        const int r0 = m0 + wm0 + 16 * i + g;
#pragma unroll
        for (int j = 0; j < 4; ++j) {
            const int cc = n0 + wn0 + 8 * j + 2 * t;
            *(float2*)(U + (size_t)r0 * DOUT + cc)       = make_float2(acc[i][j][0], acc[i][j][1]);
            *(float2*)(U + (size_t)(r0 + 8) * DOUT + cc) = make_float2(acc[i][j][2], acc[i][j][3]);
        }
    }
}

// ---------------------------------------------------------------------------
// Kernel 8: final blend + normalize
// ---------------------------------------------------------------------------
__global__ void final_kernel(const float* __restrict__ words, float* __restrict__ out) {
    const int r = blockIdx.x;
    const int tid = threadIdx.x;
    __shared__ float s_l;
    if (tid < 32) {
        float L = 0.f;
        for (int c = tid; c < NLT; c += 32) L += g_lpart[(size_t)r * NLT + c];
#pragma unroll
        for (int o = 16; o; o >>= 1) L += __shfl_xor_sync(0xffffffffu, L, o);
        if (tid == 0) s_l = L;
    }
    __syncthreads();
    if (tid >= D_DIM) return;
    const float m = g_m[r];
    const float pdef = __expf(g_sdef[r] - m);
    const float inv = 1.f / (s_l + pdef);
    const int ui = r * DOUT + tid;
    float u = 0.f;
#pragma unroll
    for (int s = 0; s < NSPLIT; ++s) u += g_U[s][ui];
    out[(size_t)r * D_DIM + tid] = (u + pdef * words[(size_t)r * D_DIM + tid]) * inv;
}

// ---------------------------------------------------------------------------
// kernel_launch
// ---------------------------------------------------------------------------
extern "C" void kernel_launch(void* const* d_in, const int* in_sizes, int n_in,
                              void* d_out, int out_size) {
    const float* words = nullptr;
    const float* vocab = nullptr;
    const float* de    = nullptr;
    const float* W     = nullptr;
    for (int i = 0; i < n_in; ++i) {
        switch (in_sizes[i]) {
            case N_ROWS * D_DIM: words = (const float*)d_in[i]; break;
            case V_SIZE * D_DIM: vocab = (const float*)d_in[i]; break;
            case D_DIM:          de    = (const float*)d_in[i]; break;
            case D_DIM * D_DIM:  W     = (const float*)d_in[i]; break;
            default: break;
        }
    }
    float* out = (float*)d_out;

    y_prep_kernel<<<dim3(KP / 16, N_ROWS / 16), dim3(16, 16)>>>(words, W);
    v_prep_kernel<<<(VP * KP) / 256, 256>>>(vocab);
    vt_prep_kernel<<<(DOUT * VP) / 256, 256>>>(vocab);
    sdef_kernel<<<(N_ROWS * 32) / 256, 256>>>(de);

    cudaFuncSetAttribute(gemm1_kernel, cudaFuncAttributeMaxDynamicSharedMemorySize, GEMM_SMEM);
    gemm1_kernel<<<dim3(NVT, N_ROWS / BM_T), NTH, GEMM_SMEM>>>();

    reduce_m_kernel<<<(N_ROWS * 32) / 256, 256>>>();

    expsplit_kernel<<<dim3(NLT, N_ROWS), 256>>>();

    cudaFuncSetAttribute(gemm2_kernel, cudaFuncAttributeMaxDynamicSharedMemorySize, GEMM_SMEM);
    gemm2_kernel<<<dim3(DOUT / BN_T, N_ROWS / BM_T, NSPLIT), NTH, GEMM_SMEM>>>();

    final_kernel<<<N_ROWS, 320>>>(words, out);
}